// round 2
// baseline (speedup 1.0000x reference)
#include <cuda_runtime.h>

#define Bsz 16384
#define Hd  1024
#define ODIM 128
#define RTOT (Bsz * 4)

// ---- scratch (static __device__ — no allocations allowed) ----
__device__ float g_M[(size_t)Hd * Hd];        // Wq @ Wk^T
__device__ float g_vk[Hd];                    // Wk @ bq
__device__ float g_u[(size_t)RTOT * Hd];      // z @ M
__device__ float g_y[(size_t)Bsz * Hd];       // sum_s w_s z_s

// ---- tiled SGEMM config ----
#define BM 128
#define BN 128
#define BK 8
#define TM 8
#define TN 8

__device__ __forceinline__ const float* fsel(const float* f1, const float* f2,
                                             const float* f3, const float* f4, int t) {
    return t == 0 ? f1 : t == 1 ? f2 : t == 2 ? f3 : f4;
}

// ============================================================
// M = Wq @ Wk^T   (NT gemm, 1024x1024x1024)
// ============================================================
__global__ __launch_bounds__(256) void m_gemm_kernel(const float* __restrict__ Wq,
                                                     const float* __restrict__ Wk) {
    __shared__ float As[BK][BM];
    __shared__ float Bs[BK][BN];
    const int tid = threadIdx.x;
    const int brow = blockIdx.y * BM;
    const int bcol = blockIdx.x * BN;

    const int lrow = tid >> 1;           // 0..127
    const int lcol = (tid & 1) * 4;      // 0 or 4
    const float* aptr = Wq + (size_t)(brow + lrow) * Hd + lcol;
    const float* bptr = Wk + (size_t)(bcol + lrow) * Hd + lcol;

    const int trow = (tid >> 4) * TM;
    const int tcol = (tid & 15) * TN;

    float acc[TM][TN] = {};
    for (int k0 = 0; k0 < Hd; k0 += BK) {
        float4 av = *(const float4*)(aptr + k0);
        As[lcol + 0][lrow] = av.x; As[lcol + 1][lrow] = av.y;
        As[lcol + 2][lrow] = av.z; As[lcol + 3][lrow] = av.w;
        float4 bv4 = *(const float4*)(bptr + k0);
        Bs[lcol + 0][lrow] = bv4.x; Bs[lcol + 1][lrow] = bv4.y;
        Bs[lcol + 2][lrow] = bv4.z; Bs[lcol + 3][lrow] = bv4.w;
        __syncthreads();
#pragma unroll
        for (int kk = 0; kk < BK; kk++) {
            float a[TM], b[TN];
            *(float4*)&a[0] = *(const float4*)&As[kk][trow];
            *(float4*)&a[4] = *(const float4*)&As[kk][trow + 4];
            *(float4*)&b[0] = *(const float4*)&Bs[kk][tcol];
            *(float4*)&b[4] = *(const float4*)&Bs[kk][tcol + 4];
#pragma unroll
            for (int i = 0; i < TM; i++)
#pragma unroll
                for (int j = 0; j < TN; j++) acc[i][j] += a[i] * b[j];
        }
        __syncthreads();
    }
#pragma unroll
    for (int i = 0; i < TM; i++) {
        float* crow = g_M + (size_t)(brow + trow + i) * Hd + bcol + tcol;
        *(float4*)crow       = make_float4(acc[i][0], acc[i][1], acc[i][2], acc[i][3]);
        *(float4*)(crow + 4) = make_float4(acc[i][4], acc[i][5], acc[i][6], acc[i][7]);
    }
}

// ============================================================
// vk = Wk @ bq
// ============================================================
__global__ __launch_bounds__(256) void vk_kernel(const float* __restrict__ Wk,
                                                 const float* __restrict__ bq) {
    int warp = threadIdx.x >> 5, lane = threadIdx.x & 31;
    int row = blockIdx.x * 8 + warp;
    float s = 0.f;
    for (int m = lane; m < Hd; m += 32) s += Wk[(size_t)row * Hd + m] * bq[m];
#pragma unroll
    for (int off = 16; off; off >>= 1) s += __shfl_xor_sync(0xffffffffu, s, off);
    if (lane == 0) g_vk[row] = s;
}

// ============================================================
// u = z @ M   (z rows gathered from f1..f4, 65536x1024x1024)
// ============================================================
__global__ __launch_bounds__(256) void u_gemm_kernel(const float* __restrict__ f1,
                                                     const float* __restrict__ f2,
                                                     const float* __restrict__ f3,
                                                     const float* __restrict__ f4) {
    __shared__ float As[BK][BM];
    __shared__ float Bs[BK][BN];
    const int tid = threadIdx.x;
    const int brow = blockIdx.y * BM;
    const int bcol = blockIdx.x * BN;

    const int arow = tid >> 1;
    const int acol = (tid & 1) * 4;
    const int r = brow + arow;                 // z row: b = r>>2, t = r&3
    const float* aptr = fsel(f1, f2, f3, f4, r & 3) + (size_t)(r >> 2) * Hd + acol;

    const int brw = tid >> 5;                  // 0..7
    const int bcl = (tid & 31) * 4;
    const float* bptr = g_M + (size_t)brw * Hd + bcol + bcl;

    const int trow = (tid >> 4) * TM;
    const int tcol = (tid & 15) * TN;

    float acc[TM][TN] = {};
    for (int k0 = 0; k0 < Hd; k0 += BK) {
        float4 av = *(const float4*)(aptr + k0);
        As[acol + 0][arow] = av.x; As[acol + 1][arow] = av.y;
        As[acol + 2][arow] = av.z; As[acol + 3][arow] = av.w;
        *(float4*)&Bs[brw][bcl] = *(const float4*)(bptr + (size_t)k0 * Hd);
        __syncthreads();
#pragma unroll
        for (int kk = 0; kk < BK; kk++) {
            float a[TM], b[TN];
            *(float4*)&a[0] = *(const float4*)&As[kk][trow];
            *(float4*)&a[4] = *(const float4*)&As[kk][trow + 4];
            *(float4*)&b[0] = *(const float4*)&Bs[kk][tcol];
            *(float4*)&b[4] = *(const float4*)&Bs[kk][tcol + 4];
#pragma unroll
            for (int i = 0; i < TM; i++)
#pragma unroll
                for (int j = 0; j < TN; j++) acc[i][j] += a[i] * b[j];
        }
        __syncthreads();
    }
#pragma unroll
    for (int i = 0; i < TM; i++) {
        float* crow = g_u + (size_t)(brow + trow + i) * Hd + bcol + tcol;
        *(float4*)crow       = make_float4(acc[i][0], acc[i][1], acc[i][2], acc[i][3]);
        *(float4*)(crow + 4) = make_float4(acc[i][4], acc[i][5], acc[i][6], acc[i][7]);
    }
}

// ============================================================
// per-batch: G_ts = u_t . z_s ; logits += z_s.vk ; softmax ;
// w_s = sum_t p_ts ; y = sum_s w_s z_s
// ============================================================
__global__ __launch_bounds__(128) void attn_kernel(const float* __restrict__ f1,
                                                   const float* __restrict__ f2,
                                                   const float* __restrict__ f3,
                                                   const float* __restrict__ f4) {
    const int b = blockIdx.x, tid = threadIdx.x;
    __shared__ float sz[4][Hd];
    __shared__ float su[4][Hd];

#pragma unroll
    for (int t = 0; t < 4; t++) {
        const float4* src  = (const float4*)(fsel(f1, f2, f3, f4, t) + (size_t)b * Hd);
        const float4* usrc = (const float4*)(g_u + ((size_t)b * 4 + t) * Hd);
        for (int jj = tid; jj < Hd / 4; jj += 128) {
            ((float4*)sz[t])[jj] = src[jj];
            ((float4*)su[t])[jj] = usrc[jj];
        }
    }
    __syncthreads();

    float aG[16] = {}, aC[4] = {};
    for (int j = tid; j < Hd; j += 128) {
        float z0 = sz[0][j], z1 = sz[1][j], z2 = sz[2][j], z3 = sz[3][j];
        float u0 = su[0][j], u1 = su[1][j], u2 = su[2][j], u3 = su[3][j];
        float vkj = g_vk[j];
        aG[0]  += u0 * z0; aG[1]  += u0 * z1; aG[2]  += u0 * z2; aG[3]  += u0 * z3;
        aG[4]  += u1 * z0; aG[5]  += u1 * z1; aG[6]  += u1 * z2; aG[7]  += u1 * z3;
        aG[8]  += u2 * z0; aG[9]  += u2 * z1; aG[10] += u2 * z2; aG[11] += u2 * z3;
        aG[12] += u3 * z0; aG[13] += u3 * z1; aG[14] += u3 * z2; aG[15] += u3 * z3;
        aC[0] += z0 * vkj; aC[1] += z1 * vkj; aC[2] += z2 * vkj; aC[3] += z3 * vkj;
    }
#pragma unroll
    for (int a = 0; a < 16; a++)
#pragma unroll
        for (int off = 16; off; off >>= 1) aG[a] += __shfl_xor_sync(0xffffffffu, aG[a], off);
#pragma unroll
    for (int a = 0; a < 4; a++)
#pragma unroll
        for (int off = 16; off; off >>= 1) aC[a] += __shfl_xor_sync(0xffffffffu, aC[a], off);

    __shared__ float rbuf[4][20];
    __shared__ float sw[4];
    const int warp = tid >> 5, lane = tid & 31;
    if (lane == 0) {
#pragma unroll
        for (int a = 0; a < 16; a++) rbuf[warp][a] = aG[a];
#pragma unroll
        for (int a = 0; a < 4; a++) rbuf[warp][16 + a] = aC[a];
    }
    __syncthreads();
    if (tid == 0) {
        float L[20];
#pragma unroll
        for (int a = 0; a < 20; a++) L[a] = rbuf[0][a] + rbuf[1][a] + rbuf[2][a] + rbuf[3][a];
        float w[4] = {0.f, 0.f, 0.f, 0.f};
#pragma unroll
        for (int t = 0; t < 4; t++) {
            float l0 = L[t * 4 + 0] + L[16];
            float l1 = L[t * 4 + 1] + L[17];
            float l2 = L[t * 4 + 2] + L[18];
            float l3 = L[t * 4 + 3] + L[19];
            float m = fmaxf(fmaxf(l0, l1), fmaxf(l2, l3));
            float e0 = expf(l0 - m), e1 = expf(l1 - m), e2 = expf(l2 - m), e3 = expf(l3 - m);
            float inv = 1.f / (e0 + e1 + e2 + e3);
            w[0] += e0 * inv; w[1] += e1 * inv; w[2] += e2 * inv; w[3] += e3 * inv;
        }
        sw[0] = w[0]; sw[1] = w[1]; sw[2] = w[2]; sw[3] = w[3];
    }
    __syncthreads();
    const float w0 = sw[0], w1 = sw[1], w2 = sw[2], w3 = sw[3];
    float4* ydst = (float4*)(g_y + (size_t)b * Hd);
    for (int jj = tid; jj < Hd / 4; jj += 128) {
        float4 z0 = ((float4*)sz[0])[jj], z1 = ((float4*)sz[1])[jj];
        float4 z2 = ((float4*)sz[2])[jj], z3 = ((float4*)sz[3])[jj];
        float4 o;
        o.x = w0 * z0.x + w1 * z1.x + w2 * z2.x + w3 * z3.x;
        o.y = w0 * z0.y + w1 * z1.y + w2 * z2.y + w3 * z3.y;
        o.z = w0 * z0.z + w1 * z1.z + w2 * z2.z + w3 * z3.z;
        o.w = w0 * z0.w + w1 * z1.w + w2 * z2.w + w3 * z3.w;
        ydst[jj] = o;
    }
}

// ============================================================
// x = y @ Wv + 4*bv   (16384x1024x1024) -> d_out[0 : B*H]
// ============================================================
__global__ __launch_bounds__(256) void x_gemm_kernel(const float* __restrict__ Wv,
                                                     const float* __restrict__ bv,
                                                     float* __restrict__ xout) {
    __shared__ float As[BK][BM];
    __shared__ float Bs[BK][BN];
    const int tid = threadIdx.x;
    const int brow = blockIdx.y * BM;
    const int bcol = blockIdx.x * BN;

    const int arow = tid >> 1;
    const int acol = (tid & 1) * 4;
    const float* aptr = g_y + (size_t)(brow + arow) * Hd + acol;

    const int brw = tid >> 5;
    const int bcl = (tid & 31) * 4;
    const float* bptr = Wv + (size_t)brw * Hd + bcol + bcl;

    const int trow = (tid >> 4) * TM;
    const int tcol = (tid & 15) * TN;

    float acc[TM][TN] = {};
    for (int k0 = 0; k0 < Hd; k0 += BK) {
        float4 av = *(const float4*)(aptr + k0);
        As[acol + 0][arow] = av.x; As[acol + 1][arow] = av.y;
        As[acol + 2][arow] = av.z; As[acol + 3][arow] = av.w;
        *(float4*)&Bs[brw][bcl] = *(const float4*)(bptr + (size_t)k0 * Hd);
        __syncthreads();
#pragma unroll
        for (int kk = 0; kk < BK; kk++) {
            float a[TM], b[TN];
            *(float4*)&a[0] = *(const float4*)&As[kk][trow];
            *(float4*)&a[4] = *(const float4*)&As[kk][trow + 4];
            *(float4*)&b[0] = *(const float4*)&Bs[kk][tcol];
            *(float4*)&b[4] = *(const float4*)&Bs[kk][tcol + 4];
#pragma unroll
            for (int i = 0; i < TM; i++)
#pragma unroll
                for (int j = 0; j < TN; j++) acc[i][j] += a[i] * b[j];
        }
        __syncthreads();
    }
    float bb[TN];
#pragma unroll
    for (int j = 0; j < TN; j++) bb[j] = 4.f * bv[bcol + tcol + j];
#pragma unroll
    for (int i = 0; i < TM; i++) {
        float* crow = xout + (size_t)(brow + trow + i) * Hd + bcol + tcol;
        *(float4*)crow       = make_float4(acc[i][0] + bb[0], acc[i][1] + bb[1],
                                           acc[i][2] + bb[2], acc[i][3] + bb[3]);
        *(float4*)(crow + 4) = make_float4(acc[i][4] + bb[4], acc[i][5] + bb[5],
                                           acc[i][6] + bb[6], acc[i][7] + bb[7]);
    }
}

// ============================================================
// out = softmax(x @ Wfc + bfc)  -> d_out[B*H : B*H + B*OUT]
// one block = 8 rows, 128 threads (thread = output column)
// ============================================================
__global__ __launch_bounds__(128) void fc_kernel(const float* __restrict__ x,
                                                 const float* __restrict__ Wfc,
                                                 const float* __restrict__ bfc,
                                                 float* __restrict__ oout) {
    __shared__ float sxT[Hd][8];   // 32KB, transposed x rows
    const int tid = threadIdx.x;
    const int row0 = blockIdx.x * 8;
    for (int idx = tid; idx < 8 * Hd; idx += 128) {
        int r = idx >> 10;
        int k = idx & (Hd - 1);
        sxT[k][r] = x[(size_t)(row0 + r) * Hd + k];
    }
    __syncthreads();
    float acc[8] = {};
#pragma unroll 4
    for (int k = 0; k < Hd; k++) {
        float wv = Wfc[(size_t)k * ODIM + tid];
        float4 lo = *(const float4*)&sxT[k][0];
        float4 hi = *(const float4*)&sxT[k][4];
        acc[0] += lo.x * wv; acc[1] += lo.y * wv; acc[2] += lo.z * wv; acc[3] += lo.w * wv;
        acc[4] += hi.x * wv; acc[5] += hi.y * wv; acc[6] += hi.z * wv; acc[7] += hi.w * wv;
    }
    const float bb = bfc[tid];
#pragma unroll
    for (int r = 0; r < 8; r++) acc[r] += bb;

    __shared__ float slog[8][128];
#pragma unroll
    for (int r = 0; r < 8; r++) slog[r][tid] = acc[r];
    __syncthreads();
    __shared__ float smax[8], sinv[8];
    const int warp = tid >> 5, lane = tid & 31;
#pragma unroll
    for (int rr = 0; rr < 2; rr++) {
        int r = warp * 2 + rr;
        float v0 = slog[r][lane], v1 = slog[r][lane + 32];
        float v2 = slog[r][lane + 64], v3 = slog[r][lane + 96];
        float m = fmaxf(fmaxf(v0, v1), fmaxf(v2, v3));
#pragma unroll
        for (int off = 16; off; off >>= 1) m = fmaxf(m, __shfl_xor_sync(0xffffffffu, m, off));
        float s = expf(v0 - m) + expf(v1 - m) + expf(v2 - m) + expf(v3 - m);
#pragma unroll
        for (int off = 16; off; off >>= 1) s += __shfl_xor_sync(0xffffffffu, s, off);
        if (lane == 0) { smax[r] = m; sinv[r] = 1.f / s; }
    }
    __syncthreads();
#pragma unroll
    for (int r = 0; r < 8; r++)
        oout[(size_t)(row0 + r) * ODIM + tid] = expf(acc[r] - smax[r]) * sinv[r];
}

// ============================================================
extern "C" void kernel_launch(void* const* d_in, const int* in_sizes, int n_in,
                              void* d_out, int out_size) {
    (void)in_sizes; (void)n_in; (void)out_size;
    const float* f1  = (const float*)d_in[0];
    const float* f2  = (const float*)d_in[1];
    const float* f3  = (const float*)d_in[2];
    const float* f4  = (const float*)d_in[3];
    const float* Wq  = (const float*)d_in[4];
    const float* bq  = (const float*)d_in[5];
    const float* Wk  = (const float*)d_in[6];
    // d_in[7] = bk: cancels inside softmax (constant per row) — unused
    const float* Wv  = (const float*)d_in[8];
    const float* bv  = (const float*)d_in[9];
    const float* Wfc = (const float*)d_in[10];
    const float* bfc = (const float*)d_in[11];

    float* xout = (float*)d_out;                 // [B, H]
    float* oout = xout + (size_t)Bsz * Hd;       // [B, OUT]

    m_gemm_kernel<<<dim3(Hd / BN, Hd / BM), 256>>>(Wq, Wk);
    vk_kernel<<<Hd / 8, 256>>>(Wk, bq);
    u_gemm_kernel<<<dim3(Hd / BN, RTOT / BM), 256>>>(f1, f2, f3, f4);
    attn_kernel<<<Bsz, 128>>>(f1, f2, f3, f4);
    x_gemm_kernel<<<dim3(Hd / BN, Bsz / BM), 256>>>(Wv, bv, xout);
    fc_kernel<<<Bsz / 8, 128>>>(xout, Wfc, bfc, oout);
}

// round 9
// speedup vs baseline: 1.5055x; 1.5055x over previous
#include <cuda_runtime.h>
#include <cuda_bf16.h>
#include <cstdint>

#define Bsz 16384
#define Hd  1024
#define ODIM 128
#define RTOT (Bsz * 4)

// ---- scratch (static __device__ — no allocations allowed) ----
__device__ __nv_bfloat16 g_zh[(size_t)RTOT * Hd];   // z hi
__device__ __nv_bfloat16 g_zl[(size_t)RTOT * Hd];   // z lo
__device__ __nv_bfloat16 g_Mth[(size_t)Hd * Hd];    // (WqWk^T)^T = Wk Wq^T, hi
__device__ __nv_bfloat16 g_Mtl[(size_t)Hd * Hd];    // lo
__device__ float g_vk[Hd];                          // Wk @ bq
__device__ float g_u[(size_t)RTOT * Hd];            // z @ M  (fp32)
__device__ float g_y[(size_t)Bsz * Hd];             // sum_s w_s z_s (fp32, as in R2)

// ============================================================
// helpers
// ============================================================
__device__ __forceinline__ void mma16816(float (&d)[4], const uint32_t (&a)[4],
                                         uint32_t b0, uint32_t b1) {
    asm volatile(
        "mma.sync.aligned.m16n8k16.row.col.f32.bf16.bf16.f32 "
        "{%0,%1,%2,%3}, {%4,%5,%6,%7}, {%8,%9}, {%0,%1,%2,%3};"
        : "+f"(d[0]), "+f"(d[1]), "+f"(d[2]), "+f"(d[3])
        : "r"(a[0]), "r"(a[1]), "r"(a[2]), "r"(a[3]), "r"(b0), "r"(b1));
}
__device__ __forceinline__ const float* fsel(const float* f1, const float* f2,
                                             const float* f3, const float* f4, int t) {
    return t == 0 ? f1 : t == 1 ? f2 : t == 2 ? f3 : f4;
}
__device__ __forceinline__ void split_bf16(float v, __nv_bfloat16& h, __nv_bfloat16& l) {
    h = __float2bfloat16(v);
    l = __float2bfloat16(v - __bfloat162float(h));
}

// ============================================================
// prep_z: f1..f4 -> g_zh/g_zl, row r = b*4+t
// ============================================================
__global__ __launch_bounds__(256) void prep_z_kernel(const float* __restrict__ f1,
                                                     const float* __restrict__ f2,
                                                     const float* __restrict__ f3,
                                                     const float* __restrict__ f4) {
    size_t gid = (size_t)blockIdx.x * 256 + threadIdx.x;   // over RTOT * (Hd/4)
    int r = (int)(gid >> 8);
    int jj = (int)(gid & 255);
    const float* src = fsel(f1, f2, f3, f4, r & 3) + (size_t)(r >> 2) * Hd;
    float4 v = ((const float4*)src)[jj];
    __nv_bfloat16 hx, lx, hy, ly, hz, lz, hw, lw;
    split_bf16(v.x, hx, lx); split_bf16(v.y, hy, ly);
    split_bf16(v.z, hz, lz); split_bf16(v.w, hw, lw);
    __nv_bfloat162* dh = (__nv_bfloat162*)(g_zh + (size_t)r * Hd + jj * 4);
    __nv_bfloat162* dl = (__nv_bfloat162*)(g_zl + (size_t)r * Hd + jj * 4);
    dh[0] = __halves2bfloat162(hx, hy); dh[1] = __halves2bfloat162(hz, hw);
    dl[0] = __halves2bfloat162(lx, ly); dl[1] = __halves2bfloat162(lz, lw);
}

// ============================================================
// Mt = Wk @ Wq^T -> bf16 hi/lo (SIMT fp32 GEMM, small: 1024^3)
// ============================================================
#define BM 128
#define BN 128
#define BK 8
#define TM 8
#define TN 8
__global__ __launch_bounds__(256) void mt_gemm_kernel(const float* __restrict__ Wk,
                                                      const float* __restrict__ Wq) {
    __shared__ float As[BK][BM];
    __shared__ float Bs[BK][BN];
    const int tid = threadIdx.x;
    const int brow = blockIdx.y * BM;
    const int bcol = blockIdx.x * BN;
    const int lrow = tid >> 1, lcol = (tid & 1) * 4;
    const float* aptr = Wk + (size_t)(brow + lrow) * Hd + lcol;
    const float* bptr = Wq + (size_t)(bcol + lrow) * Hd + lcol;
    const int trow = (tid >> 4) * TM, tcol = (tid & 15) * TN;
    float acc[TM][TN] = {};
    for (int k0 = 0; k0 < Hd; k0 += BK) {
        float4 av = *(const float4*)(aptr + k0);
        As[lcol + 0][lrow] = av.x; As[lcol + 1][lrow] = av.y;
        As[lcol + 2][lrow] = av.z; As[lcol + 3][lrow] = av.w;
        float4 bv4 = *(const float4*)(bptr + k0);
        Bs[lcol + 0][lrow] = bv4.x; Bs[lcol + 1][lrow] = bv4.y;
        Bs[lcol + 2][lrow] = bv4.z; Bs[lcol + 3][lrow] = bv4.w;
        __syncthreads();
#pragma unroll
        for (int kk = 0; kk < BK; kk++) {
            float a[TM], b[TN];
            *(float4*)&a[0] = *(const float4*)&As[kk][trow];
            *(float4*)&a[4] = *(const float4*)&As[kk][trow + 4];
            *(float4*)&b[0] = *(const float4*)&Bs[kk][tcol];
            *(float4*)&b[4] = *(const float4*)&Bs[kk][tcol + 4];
#pragma unroll
            for (int i = 0; i < TM; i++)
#pragma unroll
                for (int j = 0; j < TN; j++) acc[i][j] += a[i] * b[j];
        }
        __syncthreads();
    }
#pragma unroll
    for (int i = 0; i < TM; i++) {
        size_t off = (size_t)(brow + trow + i) * Hd + bcol + tcol;
#pragma unroll
        for (int j = 0; j < TN; j += 2) {
            __nv_bfloat16 h0, l0, h1, l1;
            split_bf16(acc[i][j], h0, l0);
            split_bf16(acc[i][j + 1], h1, l1);
            *(__nv_bfloat162*)(g_Mth + off + j) = __halves2bfloat162(h0, h1);
            *(__nv_bfloat162*)(g_Mtl + off + j) = __halves2bfloat162(l0, l1);
        }
    }
}

// ============================================================
// vk = Wk @ bq
// ============================================================
__global__ __launch_bounds__(256) void vk_kernel(const float* __restrict__ Wk,
                                                 const float* __restrict__ bq) {
    int warp = threadIdx.x >> 5, lane = threadIdx.x & 31;
    int row = blockIdx.x * 8 + warp;
    float s = 0.f;
    for (int m = lane; m < Hd; m += 32) s += Wk[(size_t)row * Hd + m] * bq[m];
#pragma unroll
    for (int off = 16; off; off >>= 1) s += __shfl_xor_sync(0xffffffffu, s, off);
    if (lane == 0) g_vk[row] = s;
}

// ============================================================
// u = z @ M via HMMA bf16x3 (Ah·Bh + Al·Bh + Ah·Bl, fp32 acc)
//   CTA 128x128, Kc=32, 8 warps (2x4), warp tile 64x32.
//   Static shared (40KB), plain LDG.128 prefetch + STS.128,
//   explicit per-lane LDS.32 fragment loads (no ldmatrix, no cp.async).
//   Row stride 40 bf16 (80B): fragment LDS are bank-conflict-free.
// ============================================================
#define UK 32
#define ULD 40
__global__ __launch_bounds__(256) void u_hmma_kernel() {
    __shared__ __nv_bfloat16 sAh[128][ULD];
    __shared__ __nv_bfloat16 sAl[128][ULD];
    __shared__ __nv_bfloat16 sBh[128][ULD];
    __shared__ __nv_bfloat16 sBl[128][ULD];

    const int tid = threadIdx.x;
    const int wid = tid >> 5, lane = tid & 31;
    const int warp_m = wid & 1, warp_n = wid >> 1;     // 2 x 4 warps
    const int g = lane >> 2, tg = lane & 3;
    const int row0 = blockIdx.y * 128, n0 = blockIdx.x * 128;

    const __nv_bfloat16* Ahp = g_zh + (size_t)row0 * Hd;
    const __nv_bfloat16* Alp = g_zl + (size_t)row0 * Hd;
    const __nv_bfloat16* Bhp = g_Mth + (size_t)n0 * Hd;
    const __nv_bfloat16* Blp = g_Mtl + (size_t)n0 * Hd;

    // loader: 512 granules(16B)/buffer; thread handles rows lrow and lrow+64
    const int lrow = tid >> 2, lq = tid & 3;
    const size_t goff = (size_t)lrow * Hd + lq * 8;

    uint4 pAh0, pAh1, pAl0, pAl1, pBh0, pBh1, pBl0, pBl1;
    auto ldg_chunk = [&](int c) {
        const size_t o = goff + (size_t)c * UK;
        pAh0 = *(const uint4*)(Ahp + o); pAh1 = *(const uint4*)(Ahp + o + (size_t)64 * Hd);
        pAl0 = *(const uint4*)(Alp + o); pAl1 = *(const uint4*)(Alp + o + (size_t)64 * Hd);
        pBh0 = *(const uint4*)(Bhp + o); pBh1 = *(const uint4*)(Bhp + o + (size_t)64 * Hd);
        pBl0 = *(const uint4*)(Blp + o); pBl1 = *(const uint4*)(Blp + o + (size_t)64 * Hd);
    };
    auto sts_chunk = [&]() {
        *(uint4*)&sAh[lrow][lq * 8] = pAh0; *(uint4*)&sAh[lrow + 64][lq * 8] = pAh1;
        *(uint4*)&sAl[lrow][lq * 8] = pAl0; *(uint4*)&sAl[lrow + 64][lq * 8] = pAl1;
        *(uint4*)&sBh[lrow][lq * 8] = pBh0; *(uint4*)&sBh[lrow + 64][lq * 8] = pBh1;
        *(uint4*)&sBl[lrow][lq * 8] = pBl0; *(uint4*)&sBl[lrow + 64][lq * 8] = pBl1;
    };

    const int arow = warp_m * 64 + g;
    const int brow = warp_n * 32 + g;
    float acc[4][4][4] = {};

    ldg_chunk(0);
    for (int c = 0; c < Hd / UK; c++) {
        __syncthreads();              // WAR: prior compute done reading smem
        sts_chunk();
        __syncthreads();
        if (c < Hd / UK - 1) ldg_chunk(c + 1);   // overlapped with compute below

#pragma unroll
        for (int ks = 0; ks < 2; ks++) {
            const int kc = ks * 16 + 2 * tg;
            uint32_t ah[4][4], al[4][4], bh[4][2], bl[4][2];
#pragma unroll
            for (int mf = 0; mf < 4; mf++) {
                const int r = arow + mf * 16;
                ah[mf][0] = *(const uint32_t*)&sAh[r][kc];
                ah[mf][1] = *(const uint32_t*)&sAh[r + 8][kc];
                ah[mf][2] = *(const uint32_t*)&sAh[r][kc + 8];
                ah[mf][3] = *(const uint32_t*)&sAh[r + 8][kc + 8];
                al[mf][0] = *(const uint32_t*)&sAl[r][kc];
                al[mf][1] = *(const uint32_t*)&sAl[r + 8][kc];
                al[mf][2] = *(const uint32_t*)&sAl[r][kc + 8];
                al[mf][3] = *(const uint32_t*)&sAl[r + 8][kc + 8];
            }
#pragma unroll
            for (int nf = 0; nf < 4; nf++) {
                const int r = brow + nf * 8;
                bh[nf][0] = *(const uint32_t*)&sBh[r][kc];
                bh[nf][1] = *(const uint32_t*)&sBh[r][kc + 8];
                bl[nf][0] = *(const uint32_t*)&sBl[r][kc];
                bl[nf][1] = *(const uint32_t*)&sBl[r][kc + 8];
            }
#pragma unroll
            for (int mf = 0; mf < 4; mf++)
#pragma unroll
                for (int nf = 0; nf < 4; nf++) {
                    mma16816(acc[mf][nf], ah[mf], bh[nf][0], bh[nf][1]);
                    mma16816(acc[mf][nf], al[mf], bh[nf][0], bh[nf][1]);
                    mma16816(acc[mf][nf], ah[mf], bl[nf][0], bl[nf][1]);
                }
        }
    }

    // epilogue: c0,c1 = row g, cols 2tg..; c2,c3 = row g+8
#pragma unroll
    for (int mf = 0; mf < 4; mf++) {
        const int rg = row0 + warp_m * 64 + mf * 16 + g;
#pragma unroll
        for (int nf = 0; nf < 4; nf++) {
            const int cg = n0 + warp_n * 32 + nf * 8 + tg * 2;
            *(float2*)(g_u + (size_t)rg * Hd + cg) =
                make_float2(acc[mf][nf][0], acc[mf][nf][1]);
            *(float2*)(g_u + (size_t)(rg + 8) * Hd + cg) =
                make_float2(acc[mf][nf][2], acc[mf][nf][3]);
        }
    }
}

// ============================================================
// per-batch attention (R2-proven): logits via u,z; softmax; y fp32
// ============================================================
__global__ __launch_bounds__(128) void attn_kernel(const float* __restrict__ f1,
                                                   const float* __restrict__ f2,
                                                   const float* __restrict__ f3,
                                                   const float* __restrict__ f4) {
    const int b = blockIdx.x, tid = threadIdx.x;
    __shared__ float sz[4][Hd];
    __shared__ float su[4][Hd];
#pragma unroll
    for (int t = 0; t < 4; t++) {
        const float4* src  = (const float4*)(fsel(f1, f2, f3, f4, t) + (size_t)b * Hd);
        const float4* usrc = (const float4*)(g_u + ((size_t)b * 4 + t) * Hd);
        for (int jj = tid; jj < Hd / 4; jj += 128) {
            ((float4*)sz[t])[jj] = src[jj];
            ((float4*)su[t])[jj] = usrc[jj];
        }
    }
    __syncthreads();

    float aG[16] = {}, aC[4] = {};
    for (int j = tid; j < Hd; j += 128) {
        float z0 = sz[0][j], z1 = sz[1][j], z2 = sz[2][j], z3 = sz[3][j];
        float u0 = su[0][j], u1 = su[1][j], u2 = su[2][j], u3 = su[3][j];
        float vkj = g_vk[j];
        aG[0]  += u0 * z0; aG[1]  += u0 * z1; aG[2]  += u0 * z2; aG[3]  += u0 * z3;
        aG[4]  += u1 * z0; aG[5]  += u1 * z1; aG[6]  += u1 * z2; aG[7]  += u1 * z3;
        aG[8]  += u2 * z0; aG[9]  += u2 * z1; aG[10] += u2 * z2; aG[11] += u2 * z3;
        aG[12] += u3 * z0; aG[13] += u3 * z1; aG[14] += u3 * z2; aG[15] += u3 * z3;
        aC[0] += z0 * vkj; aC[1] += z1 * vkj; aC[2] += z2 * vkj; aC[3] += z3 * vkj;
    }
#pragma unroll
    for (int a = 0; a < 16; a++)
#pragma unroll
        for (int off = 16; off; off >>= 1) aG[a] += __shfl_xor_sync(0xffffffffu, aG[a], off);
#pragma unroll
    for (int a = 0; a < 4; a++)
#pragma unroll
        for (int off = 16; off; off >>= 1) aC[a] += __shfl_xor_sync(0xffffffffu, aC[a], off);

    __shared__ float rbuf[4][20];
    __shared__ float sw[4];
    const int warp = tid >> 5, lane = tid & 31;
    if (lane == 0) {
#pragma unroll
        for (int a = 0; a < 16; a++) rbuf[warp][a] = aG[a];
#pragma unroll
        for (int a = 0; a < 4; a++) rbuf[warp][16 + a] = aC[a];
    }
    __syncthreads();
    if (tid == 0) {
        float L[20];
#pragma unroll
        for (int a = 0; a < 20; a++) L[a] = rbuf[0][a] + rbuf[1][a] + rbuf[2][a] + rbuf[3][a];
        float w[4] = {0.f, 0.f, 0.f, 0.f};
#pragma unroll
        for (int t = 0; t < 4; t++) {
            float l0 = L[t * 4 + 0] + L[16];
            float l1 = L[t * 4 + 1] + L[17];
            float l2 = L[t * 4 + 2] + L[18];
            float l3 = L[t * 4 + 3] + L[19];
            float m = fmaxf(fmaxf(l0, l1), fmaxf(l2, l3));
            float e0 = expf(l0 - m), e1 = expf(l1 - m), e2 = expf(l2 - m), e3 = expf(l3 - m);
            float inv = 1.f / (e0 + e1 + e2 + e3);
            w[0] += e0 * inv; w[1] += e1 * inv; w[2] += e2 * inv; w[3] += e3 * inv;
        }
        sw[0] = w[0]; sw[1] = w[1]; sw[2] = w[2]; sw[3] = w[3];
    }
    __syncthreads();
    const float w0 = sw[0], w1 = sw[1], w2 = sw[2], w3 = sw[3];
    float4* ydst = (float4*)(g_y + (size_t)b * Hd);
    for (int jj = tid; jj < Hd / 4; jj += 128) {
        float4 z0 = ((float4*)sz[0])[jj], z1 = ((float4*)sz[1])[jj];
        float4 z2 = ((float4*)sz[2])[jj], z3 = ((float4*)sz[3])[jj];
        float4 o;
        o.x = w0 * z0.x + w1 * z1.x + w2 * z2.x + w3 * z3.x;
        o.y = w0 * z0.y + w1 * z1.y + w2 * z2.y + w3 * z3.y;
        o.z = w0 * z0.z + w1 * z1.z + w2 * z2.z + w3 * z3.z;
        o.w = w0 * z0.w + w1 * z1.w + w2 * z2.w + w3 * z3.w;
        ydst[jj] = o;
    }
}

// ============================================================
// x = y @ Wv + 4*bv   (R2-proven SIMT fp32 GEMM) -> d_out[0 : B*H]
// ============================================================
__global__ __launch_bounds__(256) void x_gemm_kernel(const float* __restrict__ Wv,
                                                     const float* __restrict__ bv,
                                                     float* __restrict__ xout) {
    __shared__ float As[BK][BM];
    __shared__ float Bs[BK][BN];
    const int tid = threadIdx.x;
    const int brow = blockIdx.y * BM;
    const int bcol = blockIdx.x * BN;

    const int arow = tid >> 1;
    const int acol = (tid & 1) * 4;
    const float* aptr = g_y + (size_t)(brow + arow) * Hd + acol;

    const int brw = tid >> 5;
    const int bcl = (tid & 31) * 4;
    const float* bptr = Wv + (size_t)brw * Hd + bcol + bcl;

    const int trow = (tid >> 4) * TM;
    const int tcol = (tid & 15) * TN;

    float acc[TM][TN] = {};
    for (int k0 = 0; k0 < Hd; k0 += BK) {
        float4 av = *(const float4*)(aptr + k0);
        As[acol + 0][arow] = av.x; As[acol + 1][arow] = av.y;
        As[acol + 2][arow] = av.z; As[acol + 3][arow] = av.w;
        *(float4*)&Bs[brw][bcl] = *(const float4*)(bptr + (size_t)k0 * Hd);
        __syncthreads();
#pragma unroll
        for (int kk = 0; kk < BK; kk++) {
            float a[TM], b[TN];
            *(float4*)&a[0] = *(const float4*)&As[kk][trow];
            *(float4*)&a[4] = *(const float4*)&As[kk][trow + 4];
            *(float4*)&b[0] = *(const float4*)&Bs[kk][tcol];
            *(float4*)&b[4] = *(const float4*)&Bs[kk][tcol + 4];
#pragma unroll
            for (int i = 0; i < TM; i++)
#pragma unroll
                for (int j = 0; j < TN; j++) acc[i][j] += a[i] * b[j];
        }
        __syncthreads();
    }
    float bb[TN];
#pragma unroll
    for (int j = 0; j < TN; j++) bb[j] = 4.f * bv[bcol + tcol + j];
#pragma unroll
    for (int i = 0; i < TM; i++) {
        float* crow = xout + (size_t)(brow + trow + i) * Hd + bcol + tcol;
        *(float4*)crow       = make_float4(acc[i][0] + bb[0], acc[i][1] + bb[1],
                                           acc[i][2] + bb[2], acc[i][3] + bb[3]);
        *(float4*)(crow + 4) = make_float4(acc[i][4] + bb[4], acc[i][5] + bb[5],
                                           acc[i][6] + bb[6], acc[i][7] + bb[7]);
    }
}

// ============================================================
// out = softmax(x @ Wfc + bfc)  (R2-proven)
// ============================================================
__global__ __launch_bounds__(128) void fc_kernel(const float* __restrict__ x,
                                                 const float* __restrict__ Wfc,
                                                 const float* __restrict__ bfc,
                                                 float* __restrict__ oout) {
    __shared__ float sxT[Hd][8];
    const int tid = threadIdx.x;
    const int row0 = blockIdx.x * 8;
    for (int idx = tid; idx < 8 * Hd; idx += 128) {
        int r = idx >> 10;
        int k = idx & (Hd - 1);
        sxT[k][r] = x[(size_t)(row0 + r) * Hd + k];
    }
    __syncthreads();
    float acc[8] = {};
#pragma unroll 4
    for (int k = 0; k < Hd; k++) {
        float wv = Wfc[(size_t)k * ODIM + tid];
        float4 lo = *(const float4*)&sxT[k][0];
        float4 hi = *(const float4*)&sxT[k][4];
        acc[0] += lo.x * wv; acc[1] += lo.y * wv; acc[2] += lo.z * wv; acc[3] += lo.w * wv;
        acc[4] += hi.x * wv; acc[5] += hi.y * wv; acc[6] += hi.z * wv; acc[7] += hi.w * wv;
    }
    const float bb = bfc[tid];
#pragma unroll
    for (int r = 0; r < 8; r++) acc[r] += bb;

    __shared__ float slog[8][128];
#pragma unroll
    for (int r = 0; r < 8; r++) slog[r][tid] = acc[r];
    __syncthreads();
    __shared__ float smax[8], sinv[8];
    const int warp = tid >> 5, lane = tid & 31;
#pragma unroll
    for (int rr = 0; rr < 2; rr++) {
        int r = warp * 2 + rr;
        float v0 = slog[r][lane], v1 = slog[r][lane + 32];
        float v2 = slog[r][lane + 64], v3 = slog[r][lane + 96];
        float m = fmaxf(fmaxf(v0, v1), fmaxf(v2, v3));
#pragma unroll
        for (int off = 16; off; off >>= 1) m = fmaxf(m, __shfl_xor_sync(0xffffffffu, m, off));
        float s = expf(v0 - m) + expf(v1 - m) + expf(v2 - m) + expf(v3 - m);
#pragma unroll
        for (int off = 16; off; off >>= 1) s += __shfl_xor_sync(0xffffffffu, s, off);
        if (lane == 0) { smax[r] = m; sinv[r] = 1.f / s; }
    }
    __syncthreads();
#pragma unroll
    for (int r = 0; r < 8; r++)
        oout[(size_t)(row0 + r) * ODIM + tid] = expf(acc[r] - smax[r]) * sinv[r];
}

// ============================================================
extern "C" void kernel_launch(void* const* d_in, const int* in_sizes, int n_in,
                              void* d_out, int out_size) {
    (void)in_sizes; (void)n_in; (void)out_size;
    const float* f1  = (const float*)d_in[0];
    const float* f2  = (const float*)d_in[1];
    const float* f3  = (const float*)d_in[2];
    const float* f4  = (const float*)d_in[3];
    const float* Wq  = (const float*)d_in[4];
    const float* bq  = (const float*)d_in[5];
    const float* Wk  = (const float*)d_in[6];
    // d_in[7] = bk: cancels inside softmax — unused
    const float* Wv  = (const float*)d_in[8];
    const float* bv  = (const float*)d_in[9];
    const float* Wfc = (const float*)d_in[10];
    const float* bfc = (const float*)d_in[11];

    float* xout = (float*)d_out;                 // [B, H]
    float* oout = xout + (size_t)Bsz * Hd;       // [B, OUT]

    // bf16 split conversions + small precomputes
    prep_z_kernel<<<(RTOT * (Hd / 4)) / 256, 256>>>(f1, f2, f3, f4);
    mt_gemm_kernel<<<dim3(Hd / BN, Hd / BM), 256>>>(Wk, Wq);
    vk_kernel<<<Hd / 8, 256>>>(Wk, bq);

    // u = z @ M  (HMMA bf16x3, static smem, no cp.async/ldmatrix)
    u_hmma_kernel<<<dim3(Hd / 128, RTOT / 128), 256>>>();

    // attention reduce -> y (fp32, R2-proven)
    attn_kernel<<<Bsz, 128>>>(f1, f2, f3, f4);

    // x = y @ Wv + 4*bv  (SIMT fp32, R2-proven)
    x_gemm_kernel<<<dim3(Hd / BN, Bsz / BM), 256>>>(Wv, bv, xout);

    // out = softmax(x @ Wfc + bfc)
    fc_kernel<<<Bsz / 8, 128>>>(xout, Wfc, bfc, oout);
}

// round 11
// speedup vs baseline: 1.7124x; 1.1374x over previous
#include <cuda_runtime.h>
#include <cuda_bf16.h>
#include <cstdint>

#define Bsz 16384
#define Hd  1024
#define ODIM 128
#define RTOT (Bsz * 4)

// ---- scratch (static __device__ — no allocations allowed) ----
__device__ __nv_bfloat16 g_zh[(size_t)RTOT * Hd];   // z hi
__device__ __nv_bfloat16 g_zl[(size_t)RTOT * Hd];   // z lo
__device__ __nv_bfloat16 g_Mth[(size_t)Hd * Hd];    // (WqWk^T)^T = Wk Wq^T, hi
__device__ __nv_bfloat16 g_Mtl[(size_t)Hd * Hd];    // lo
__device__ __nv_bfloat16 g_Wvth[(size_t)Hd * Hd];   // Wv^T hi
__device__ __nv_bfloat16 g_Wvtl[(size_t)Hd * Hd];   // Wv^T lo
__device__ float g_vk[Hd];                          // Wk @ bq
__device__ float g_u[(size_t)RTOT * Hd];            // z @ M  (fp32)
__device__ __nv_bfloat16 g_yh[(size_t)Bsz * Hd];    // y hi
__device__ __nv_bfloat16 g_yl[(size_t)Bsz * Hd];    // y lo

// ============================================================
// helpers
// ============================================================
__device__ __forceinline__ void mma16816(float (&d)[4], const uint32_t (&a)[4],
                                         uint32_t b0, uint32_t b1) {
    asm volatile(
        "mma.sync.aligned.m16n8k16.row.col.f32.bf16.bf16.f32 "
        "{%0,%1,%2,%3}, {%4,%5,%6,%7}, {%8,%9}, {%0,%1,%2,%3};"
        : "+f"(d[0]), "+f"(d[1]), "+f"(d[2]), "+f"(d[3])
        : "r"(a[0]), "r"(a[1]), "r"(a[2]), "r"(a[3]), "r"(b0), "r"(b1));
}
__device__ __forceinline__ const float* fsel(const float* f1, const float* f2,
                                             const float* f3, const float* f4, int t) {
    return t == 0 ? f1 : t == 1 ? f2 : t == 2 ? f3 : f4;
}
__device__ __forceinline__ void split_bf16(float v, __nv_bfloat16& h, __nv_bfloat16& l) {
    h = __float2bfloat16(v);
    l = __float2bfloat16(v - __bfloat162float(h));
}

// ============================================================
// prep_z: f1..f4 -> g_zh/g_zl, row r = b*4+t
// ============================================================
__global__ __launch_bounds__(256) void prep_z_kernel(const float* __restrict__ f1,
                                                     const float* __restrict__ f2,
                                                     const float* __restrict__ f3,
                                                     const float* __restrict__ f4) {
    size_t gid = (size_t)blockIdx.x * 256 + threadIdx.x;   // over RTOT * (Hd/4)
    int r = (int)(gid >> 8);
    int jj = (int)(gid & 255);
    const float* src = fsel(f1, f2, f3, f4, r & 3) + (size_t)(r >> 2) * Hd;
    float4 v = ((const float4*)src)[jj];
    __nv_bfloat16 hx, lx, hy, ly, hz, lz, hw, lw;
    split_bf16(v.x, hx, lx); split_bf16(v.y, hy, ly);
    split_bf16(v.z, hz, lz); split_bf16(v.w, hw, lw);
    __nv_bfloat162* dh = (__nv_bfloat162*)(g_zh + (size_t)r * Hd + jj * 4);
    __nv_bfloat162* dl = (__nv_bfloat162*)(g_zl + (size_t)r * Hd + jj * 4);
    dh[0] = __halves2bfloat162(hx, hy); dh[1] = __halves2bfloat162(hz, hw);
    dl[0] = __halves2bfloat162(lx, ly); dl[1] = __halves2bfloat162(lz, lw);
}

// ============================================================
// Mt = Wk @ Wq^T -> bf16 hi/lo (SIMT fp32 GEMM, small: 1024^3)
// ============================================================
#define BM 128
#define BN 128
#define BK 8
#define TM 8
#define TN 8
__global__ __launch_bounds__(256) void mt_gemm_kernel(const float* __restrict__ Wk,
                                                      const float* __restrict__ Wq) {
    __shared__ float As[BK][BM];
    __shared__ float Bs[BK][BN];
    const int tid = threadIdx.x;
    const int brow = blockIdx.y * BM;
    const int bcol = blockIdx.x * BN;
    const int lrow = tid >> 1, lcol = (tid & 1) * 4;
    const float* aptr = Wk + (size_t)(brow + lrow) * Hd + lcol;
    const float* bptr = Wq + (size_t)(bcol + lrow) * Hd + lcol;
    const int trow = (tid >> 4) * TM, tcol = (tid & 15) * TN;
    float acc[TM][TN] = {};
    for (int k0 = 0; k0 < Hd; k0 += BK) {
        float4 av = *(const float4*)(aptr + k0);
        As[lcol + 0][lrow] = av.x; As[lcol + 1][lrow] = av.y;
        As[lcol + 2][lrow] = av.z; As[lcol + 3][lrow] = av.w;
        float4 bv4 = *(const float4*)(bptr + k0);
        Bs[lcol + 0][lrow] = bv4.x; Bs[lcol + 1][lrow] = bv4.y;
        Bs[lcol + 2][lrow] = bv4.z; Bs[lcol + 3][lrow] = bv4.w;
        __syncthreads();
#pragma unroll
        for (int kk = 0; kk < BK; kk++) {
            float a[TM], b[TN];
            *(float4*)&a[0] = *(const float4*)&As[kk][trow];
            *(float4*)&a[4] = *(const float4*)&As[kk][trow + 4];
            *(float4*)&b[0] = *(const float4*)&Bs[kk][tcol];
            *(float4*)&b[4] = *(const float4*)&Bs[kk][tcol + 4];
#pragma unroll
            for (int i = 0; i < TM; i++)
#pragma unroll
                for (int j = 0; j < TN; j++) acc[i][j] += a[i] * b[j];
        }
        __syncthreads();
    }
#pragma unroll
    for (int i = 0; i < TM; i++) {
        size_t off = (size_t)(brow + trow + i) * Hd + bcol + tcol;
#pragma unroll
        for (int j = 0; j < TN; j += 2) {
            __nv_bfloat16 h0, l0, h1, l1;
            split_bf16(acc[i][j], h0, l0);
            split_bf16(acc[i][j + 1], h1, l1);
            *(__nv_bfloat162*)(g_Mth + off + j) = __halves2bfloat162(h0, h1);
            *(__nv_bfloat162*)(g_Mtl + off + j) = __halves2bfloat162(l0, l1);
        }
    }
}

// ============================================================
// Wvt[n][k] = Wv[k][n] -> bf16 hi/lo
// ============================================================
__global__ __launch_bounds__(256) void wvt_kernel(const float* __restrict__ Wv) {
    __shared__ float tile[32][33];
    const int tx = threadIdx.x & 31, ty8 = threadIdx.x >> 5;  // 32x8
    const int n0 = blockIdx.x * 32, k0 = blockIdx.y * 32;
#pragma unroll
    for (int r = 0; r < 4; r++) {
        int ky = ty8 + r * 8;
        tile[ky][tx] = Wv[(size_t)(k0 + ky) * Hd + n0 + tx];
    }
    __syncthreads();
#pragma unroll
    for (int r = 0; r < 4; r++) {
        int ny = ty8 + r * 8;
        float v = tile[tx][ny];
        __nv_bfloat16 h, l;
        split_bf16(v, h, l);
        g_Wvth[(size_t)(n0 + ny) * Hd + k0 + tx] = h;
        g_Wvtl[(size_t)(n0 + ny) * Hd + k0 + tx] = l;
    }
}

// ============================================================
// vk = Wk @ bq
// ============================================================
__global__ __launch_bounds__(256) void vk_kernel(const float* __restrict__ Wk,
                                                 const float* __restrict__ bq) {
    int warp = threadIdx.x >> 5, lane = threadIdx.x & 31;
    int row = blockIdx.x * 8 + warp;
    float s = 0.f;
    for (int m = lane; m < Hd; m += 32) s += Wk[(size_t)row * Hd + m] * bq[m];
#pragma unroll
    for (int off = 16; off; off >>= 1) s += __shfl_xor_sync(0xffffffffu, s, off);
    if (lane == 0) g_vk[row] = s;
}

// ============================================================
// HMMA bf16x3 GEMM body (device-side; pointers bound IN DEVICE CODE).
//   C[rows,1024] = A@B^T (+ biasScale*bias)
//   CTA 128x128, Kc=16, 8 warps (2x4), warp tile 64x32.
//   Double-buffered static SMEM: 2 stages x 4 bufs x 128 x 24-stride = 48KB.
//   Explicit per-lane LDS.32 fragment loads (R9-proven mapping).
// ============================================================
#define HK 16
#define HLD 24    // row stride in bf16 (48B): 12 words/row -> conflict-free frags
template <bool BIAS>
__device__ __forceinline__ void hmma_gemm_body(
    const __nv_bfloat16* __restrict__ Ah, const __nv_bfloat16* __restrict__ Al,
    const __nv_bfloat16* __restrict__ Bh, const __nv_bfloat16* __restrict__ Bl,
    float* __restrict__ C, const float* __restrict__ bias, float biasScale) {
    __shared__ __nv_bfloat16 sm[2][4][128][HLD];   // [stage][buf][row][col]

    const int tid = threadIdx.x;
    const int wid = tid >> 5, lane = tid & 31;
    const int warp_m = wid & 1, warp_n = wid >> 1;  // 2 x 4
    const int g = lane >> 2, tg = lane & 3;
    const int row0 = blockIdx.y * 128, n0 = blockIdx.x * 128;

    const __nv_bfloat16* ptr[4] = {Ah + (size_t)row0 * Hd, Al + (size_t)row0 * Hd,
                                   Bh + (size_t)n0 * Hd,  Bl + (size_t)n0 * Hd};

    // loader: per stage 4 bufs x 128 rows x 2 granules(16B) = 1024; 4/thread
    const int lrow = tid >> 1, lq = tid & 1;
    const size_t goff = (size_t)lrow * Hd + lq * 8;

    uint4 p[4];
    auto ldg_chunk = [&](int c) {
        const size_t o = goff + (size_t)c * HK;
#pragma unroll
        for (int b = 0; b < 4; b++) p[b] = *(const uint4*)(ptr[b] + o);
    };
    auto sts_chunk = [&](int s) {
#pragma unroll
        for (int b = 0; b < 4; b++) *(uint4*)&sm[s][b][lrow][lq * 8] = p[b];
    };

    const int arow = warp_m * 64 + g;
    const int brow = warp_n * 32 + g;
    const int kc = 2 * tg;
    float acc[4][4][4] = {};

    ldg_chunk(0);
    sts_chunk(0);
    __syncthreads();

    for (int c = 0; c < Hd / HK; c++) {
        const int s = c & 1;
        if (c < Hd / HK - 1) ldg_chunk(c + 1);

        uint32_t ah[4][4], al[4][4], bh[4][2], bl[4][2];
#pragma unroll
        for (int mf = 0; mf < 4; mf++) {
            const int r = arow + mf * 16;
            ah[mf][0] = *(const uint32_t*)&sm[s][0][r][kc];
            ah[mf][1] = *(const uint32_t*)&sm[s][0][r + 8][kc];
            ah[mf][2] = *(const uint32_t*)&sm[s][0][r][kc + 8];
            ah[mf][3] = *(const uint32_t*)&sm[s][0][r + 8][kc + 8];
            al[mf][0] = *(const uint32_t*)&sm[s][1][r][kc];
            al[mf][1] = *(const uint32_t*)&sm[s][1][r + 8][kc];
            al[mf][2] = *(const uint32_t*)&sm[s][1][r][kc + 8];
            al[mf][3] = *(const uint32_t*)&sm[s][1][r + 8][kc + 8];
        }
#pragma unroll
        for (int nf = 0; nf < 4; nf++) {
            const int r = brow + nf * 8;
            bh[nf][0] = *(const uint32_t*)&sm[s][2][r][kc];
            bh[nf][1] = *(const uint32_t*)&sm[s][2][r][kc + 8];
            bl[nf][0] = *(const uint32_t*)&sm[s][3][r][kc];
            bl[nf][1] = *(const uint32_t*)&sm[s][3][r][kc + 8];
        }
#pragma unroll
        for (int mf = 0; mf < 4; mf++)
#pragma unroll
            for (int nf = 0; nf < 4; nf++) {
                mma16816(acc[mf][nf], ah[mf], bh[nf][0], bh[nf][1]);
                mma16816(acc[mf][nf], al[mf], bh[nf][0], bh[nf][1]);
                mma16816(acc[mf][nf], ah[mf], bl[nf][0], bl[nf][1]);
            }

        if (c < Hd / HK - 1) sts_chunk(s ^ 1);
        __syncthreads();
    }

    // epilogue (R9-proven): c0,c1 = row g cols 2tg..; c2,c3 = row g+8
#pragma unroll
    for (int mf = 0; mf < 4; mf++) {
        const int rg = row0 + warp_m * 64 + mf * 16 + g;
#pragma unroll
        for (int nf = 0; nf < 4; nf++) {
            const int cg = n0 + warp_n * 32 + nf * 8 + tg * 2;
            float2 v0 = make_float2(acc[mf][nf][0], acc[mf][nf][1]);
            float2 v1 = make_float2(acc[mf][nf][2], acc[mf][nf][3]);
            if (BIAS) {
                float b0 = biasScale * bias[cg], b1 = biasScale * bias[cg + 1];
                v0.x += b0; v0.y += b1; v1.x += b0; v1.y += b1;
            }
            *(float2*)(C + (size_t)rg * Hd + cg) = v0;
            *(float2*)(C + (size_t)(rg + 8) * Hd + cg) = v1;
        }
    }
}

// u = z @ M : all operands are __device__ globals, bound in device code
__global__ __launch_bounds__(256) void u_hmma_kernel() {
    hmma_gemm_body<false>(g_zh, g_zl, g_Mth, g_Mtl, g_u, nullptr, 0.f);
}
// x = y @ Wv^T + 4*bv : globals bound in device code; bv/xout are real harness ptrs
__global__ __launch_bounds__(256) void x_hmma_kernel(const float* __restrict__ bv,
                                                     float* __restrict__ xout) {
    hmma_gemm_body<true>(g_yh, g_yl, g_Wvth, g_Wvtl, xout, bv, 4.f);
}

// ============================================================
// per-batch attention: logits via u,z; softmax; y = sum_s w_s z_s (bf16 split)
// ============================================================
__global__ __launch_bounds__(128) void attn_kernel(const float* __restrict__ f1,
                                                   const float* __restrict__ f2,
                                                   const float* __restrict__ f3,
                                                   const float* __restrict__ f4) {
    const int b = blockIdx.x, tid = threadIdx.x;
    __shared__ float sz[4][Hd];
    __shared__ float su[4][Hd];
#pragma unroll
    for (int t = 0; t < 4; t++) {
        const float4* src  = (const float4*)(fsel(f1, f2, f3, f4, t) + (size_t)b * Hd);
        const float4* usrc = (const float4*)(g_u + ((size_t)b * 4 + t) * Hd);
        for (int jj = tid; jj < Hd / 4; jj += 128) {
            ((float4*)sz[t])[jj] = src[jj];
            ((float4*)su[t])[jj] = usrc[jj];
        }
    }
    __syncthreads();

    float aG[16] = {}, aC[4] = {};
    for (int j = tid; j < Hd; j += 128) {
        float z0 = sz[0][j], z1 = sz[1][j], z2 = sz[2][j], z3 = sz[3][j];
        float u0 = su[0][j], u1 = su[1][j], u2 = su[2][j], u3 = su[3][j];
        float vkj = g_vk[j];
        aG[0]  += u0 * z0; aG[1]  += u0 * z1; aG[2]  += u0 * z2; aG[3]  += u0 * z3;
        aG[4]  += u1 * z0; aG[5]  += u1 * z1; aG[6]  += u1 * z2; aG[7]  += u1 * z3;
        aG[8]  += u2 * z0; aG[9]  += u2 * z1; aG[10] += u2 * z2; aG[11] += u2 * z3;
        aG[12] += u3 * z0; aG[13] += u3 * z1; aG[14] += u3 * z2; aG[15] += u3 * z3;
        aC[0] += z0 * vkj; aC[1] += z1 * vkj; aC[2] += z2 * vkj; aC[3] += z3 * vkj;
    }
#pragma unroll
    for (int a = 0; a < 16; a++)
#pragma unroll
        for (int off = 16; off; off >>= 1) aG[a] += __shfl_xor_sync(0xffffffffu, aG[a], off);
#pragma unroll
    for (int a = 0; a < 4; a++)
#pragma unroll
        for (int off = 16; off; off >>= 1) aC[a] += __shfl_xor_sync(0xffffffffu, aC[a], off);

    __shared__ float rbuf[4][20];
    __shared__ float sw[4];
    const int warp = tid >> 5, lane = tid & 31;
    if (lane == 0) {
#pragma unroll
        for (int a = 0; a < 16; a++) rbuf[warp][a] = aG[a];
#pragma unroll
        for (int a = 0; a < 4; a++) rbuf[warp][16 + a] = aC[a];
    }
    __syncthreads();
    if (tid == 0) {
        float L[20];
#pragma unroll
        for (int a = 0; a < 20; a++) L[a] = rbuf[0][a] + rbuf[1][a] + rbuf[2][a] + rbuf[3][a];
        float w[4] = {0.f, 0.f, 0.f, 0.f};
#pragma unroll
        for (int t = 0; t < 4; t++) {
            float l0 = L[t * 4 + 0] + L[16];
            float l1 = L[t * 4 + 1] + L[17];
            float l2 = L[t * 4 + 2] + L[18];
            float l3 = L[t * 4 + 3] + L[19];
            float m = fmaxf(fmaxf(l0, l1), fmaxf(l2, l3));
            float e0 = expf(l0 - m), e1 = expf(l1 - m), e2 = expf(l2 - m), e3 = expf(l3 - m);
            float inv = 1.f / (e0 + e1 + e2 + e3);
            w[0] += e0 * inv; w[1] += e1 * inv; w[2] += e2 * inv; w[3] += e3 * inv;
        }
        sw[0] = w[0]; sw[1] = w[1]; sw[2] = w[2]; sw[3] = w[3];
    }
    __syncthreads();
    const float w0 = sw[0], w1 = sw[1], w2 = sw[2], w3 = sw[3];
    __nv_bfloat162* yh2 = (__nv_bfloat162*)(g_yh + (size_t)b * Hd);
    __nv_bfloat162* yl2 = (__nv_bfloat162*)(g_yl + (size_t)b * Hd);
    for (int jj = tid; jj < Hd / 4; jj += 128) {
        float4 z0 = ((float4*)sz[0])[jj], z1 = ((float4*)sz[1])[jj];
        float4 z2 = ((float4*)sz[2])[jj], z3 = ((float4*)sz[3])[jj];
        float4 o;
        o.x = w0 * z0.x + w1 * z1.x + w2 * z2.x + w3 * z3.x;
        o.y = w0 * z0.y + w1 * z1.y + w2 * z2.y + w3 * z3.y;
        o.z = w0 * z0.z + w1 * z1.z + w2 * z2.z + w3 * z3.z;
        o.w = w0 * z0.w + w1 * z1.w + w2 * z2.w + w3 * z3.w;
        __nv_bfloat16 hx, lx, hy, ly, hz, lz, hw, lw;
        split_bf16(o.x, hx, lx); split_bf16(o.y, hy, ly);
        split_bf16(o.z, hz, lz); split_bf16(o.w, hw, lw);
        yh2[jj * 2 + 0] = __halves2bfloat162(hx, hy);
        yh2[jj * 2 + 1] = __halves2bfloat162(hz, hw);
        yl2[jj * 2 + 0] = __halves2bfloat162(lx, ly);
        yl2[jj * 2 + 1] = __halves2bfloat162(lz, lw);
    }
}

// ============================================================
// out = softmax(x @ Wfc + bfc)
// ============================================================
__global__ __launch_bounds__(128) void fc_kernel(const float* __restrict__ x,
                                                 const float* __restrict__ Wfc,
                                                 const float* __restrict__ bfc,
                                                 float* __restrict__ oout) {
    __shared__ float sxT[Hd][8];
    const int tid = threadIdx.x;
    const int row0 = blockIdx.x * 8;
    for (int idx = tid; idx < 8 * Hd; idx += 128) {
        int r = idx >> 10;
        int k = idx & (Hd - 1);
        sxT[k][r] = x[(size_t)(row0 + r) * Hd + k];
    }
    __syncthreads();
    float acc[8] = {};
#pragma unroll 4
    for (int k = 0; k < Hd; k++) {
        float wv = Wfc[(size_t)k * ODIM + tid];
        float4 lo = *(const float4*)&sxT[k][0];
        float4 hi = *(const float4*)&sxT[k][4];
        acc[0] += lo.x * wv; acc[1] += lo.y * wv; acc[2] += lo.z * wv; acc[3] += lo.w * wv;
        acc[4] += hi.x * wv; acc[5] += hi.y * wv; acc[6] += hi.z * wv; acc[7] += hi.w * wv;
    }
    const float bb = bfc[tid];
#pragma unroll
    for (int r = 0; r < 8; r++) acc[r] += bb;

    __shared__ float slog[8][128];
#pragma unroll
    for (int r = 0; r < 8; r++) slog[r][tid] = acc[r];
    __syncthreads();
    __shared__ float smax[8], sinv[8];
    const int warp = tid >> 5, lane = tid & 31;
#pragma unroll
    for (int rr = 0; rr < 2; rr++) {
        int r = warp * 2 + rr;
        float v0 = slog[r][lane], v1 = slog[r][lane + 32];
        float v2 = slog[r][lane + 64], v3 = slog[r][lane + 96];
        float m = fmaxf(fmaxf(v0, v1), fmaxf(v2, v3));
#pragma unroll
        for (int off = 16; off; off >>= 1) m = fmaxf(m, __shfl_xor_sync(0xffffffffu, m, off));
        float s = expf(v0 - m) + expf(v1 - m) + expf(v2 - m) + expf(v3 - m);
#pragma unroll
        for (int off = 16; off; off >>= 1) s += __shfl_xor_sync(0xffffffffu, s, off);
        if (lane == 0) { smax[r] = m; sinv[r] = 1.f / s; }
    }
    __syncthreads();
#pragma unroll
    for (int r = 0; r < 8; r++)
        oout[(size_t)(row0 + r) * ODIM + tid] = expf(acc[r] - smax[r]) * sinv[r];
}

// ============================================================
extern "C" void kernel_launch(void* const* d_in, const int* in_sizes, int n_in,
                              void* d_out, int out_size) {
    (void)in_sizes; (void)n_in; (void)out_size;
    const float* f1  = (const float*)d_in[0];
    const float* f2  = (const float*)d_in[1];
    const float* f3  = (const float*)d_in[2];
    const float* f4  = (const float*)d_in[3];
    const float* Wq  = (const float*)d_in[4];
    const float* bq  = (const float*)d_in[5];
    const float* Wk  = (const float*)d_in[6];
    // d_in[7] = bk: cancels inside softmax — unused
    const float* Wv  = (const float*)d_in[8];
    const float* bv  = (const float*)d_in[9];
    const float* Wfc = (const float*)d_in[10];
    const float* bfc = (const float*)d_in[11];

    float* xout = (float*)d_out;                 // [B, H]
    float* oout = xout + (size_t)Bsz * Hd;       // [B, OUT]

    // bf16 split conversions + small precomputes
    prep_z_kernel<<<(RTOT * (Hd / 4)) / 256, 256>>>(f1, f2, f3, f4);
    mt_gemm_kernel<<<dim3(Hd / BN, Hd / BM), 256>>>(Wk, Wq);
    wvt_kernel<<<dim3(Hd / 32, Hd / 32), 256>>>(Wv);
    vk_kernel<<<Hd / 8, 256>>>(Wk, bq);

    // u = z @ M  (HMMA bf16x3, double-buffered; operands bound in device code)
    u_hmma_kernel<<<dim3(Hd / 128, RTOT / 128), 256>>>();

    // attention reduce -> y (bf16 split)
    attn_kernel<<<Bsz, 128>>>(f1, f2, f3, f4);

    // x = y @ Wv + 4*bv  (HMMA bf16x3)
    x_hmma_kernel<<<dim3(Hd / 128, Bsz / 128), 256>>>(bv, xout);

    // out = softmax(x @ Wfc + bfc)
    fc_kernel<<<Bsz / 8, 128>>>(xout, Wfc, bfc, oout);
}